// round 10
// baseline (speedup 1.0000x reference)
#include <cuda_runtime.h>
#include <math.h>

#define NC      16
#define MARGIN_F 0.3f
#define EPS_F    1e-8f
#define NTHR    256
#define GRIDB   128            // one wave; each block fully independent
#define CHUNK   256            // D-chunk staged in smem (16 rows x 256 floats)

// ---------------- device-global scratch (no allocations allowed) -----------
__device__ float        g_pr[GRIDB];
__device__ float        g_pp[GRIDB];
__device__ unsigned int g_pc[GRIDB];
__device__ int          g_done = 0;     // reset by the finalizing block

__device__ __forceinline__ float ldcg_f(const float* p) {
    float v; asm volatile("ld.global.cg.f32 %0, [%1];" : "=f"(v) : "l"(p)); return v;
}
__device__ __forceinline__ unsigned ldcg_u(const unsigned* p) {
    unsigned v; asm volatile("ld.global.cg.u32 %0, [%1];" : "=r"(v) : "l"(p)); return v;
}

__global__ void __launch_bounds__(NTHR) k_all(
    const float* __restrict__ x,        // inputs [B, D]
    const int*   __restrict__ targets,  // targets_mat [B] (int32: JAX downcast)
    const int*   __restrict__ ua,       // user_answers [T,3] (int32)
    float*       __restrict__ out,
    int B, int D, int T, int out_n)
{
    __shared__ float sX[NC * CHUNK];    // 16 KB staged row chunk
    __shared__ float sG[NC * NC];       // pair dot products
    __shared__ float sD[NC * NC];       // pair distances
    __shared__ int   s_first[NC];
    __shared__ int   s_flag;
    __shared__ float br[NTHR / 32], bp[NTHR / 32];
    __shared__ unsigned bc[NTHR / 32];
    __shared__ int   s_last;

    const int tid = threadIdx.x;
    const int bid = blockIdx.x;
    const int wid = tid >> 5;
    const int lid = tid & 31;

    // ---- Phase 1: first-occurrence scan with early exit (1 chunk whp) -----
    if (tid < NC) s_first[tid] = B;     // sentinel = absent
    __syncthreads();
    for (int base = 0; base < B; base += NTHR) {
        int i = base + tid;
        if (i < B) {
            unsigned c = (unsigned)targets[i];
            if (c < NC && i < s_first[c]) atomicMin(&s_first[c], i);
        }
        __syncthreads();
        if (tid == 0) {
            int nf = 0;
#pragma unroll
            for (int k = 0; k < NC; k++) nf += (s_first[k] < B) ? 1 : 0;
            s_flag = (nf == NC) ? 1 : 0;
        }
        __syncthreads();
        if (s_flag) break;
    }

    // ---- Phase 2: block-local 16x16 Gram matrix (chunked over D) ----------
    // Warp w owns output rows i0=2w, i1=2w+1. Lane l owns elements
    // [l*8, l*8+8) of each chunk. acc[j] accumulates partial dot(row_i, row_j).
    float acc0[NC], acc1[NC];
#pragma unroll
    for (int j = 0; j < NC; j++) { acc0[j] = 0.f; acc1[j] = 0.f; }
    const int i0 = 2 * wid, i1 = 2 * wid + 1;

    for (int c0 = 0; c0 < D; c0 += CHUNK) {
        // stage chunk: rows 0..15, cols [c0, c0+CHUNK), zero-padded
        for (int q = tid; q < NC * CHUNK; q += NTHR) {
            int r  = q >> 8;            // q / CHUNK
            int cc = q & (CHUNK - 1);
            int fi = s_first[r]; if (fi >= B) fi = 0;   // all-false argmax == 0
            int col = c0 + cc;
            sX[q] = (col < D) ? x[(size_t)fi * (size_t)D + col] : 0.f;
        }
        __syncthreads();

        float a0[8], a1[8];
#pragma unroll
        for (int e = 0; e < 8; e++) {
            a0[e] = sX[i0 * CHUNK + lid * 8 + e];
            a1[e] = sX[i1 * CHUNK + lid * 8 + e];
        }
#pragma unroll
        for (int j = 0; j < NC; j++) {
            float bj[8];
#pragma unroll
            for (int e = 0; e < 8; e++) bj[e] = sX[j * CHUNK + lid * 8 + e];
            float s0 = 0.f, s1 = 0.f;
#pragma unroll
            for (int e = 0; e < 8; e++) { s0 += a0[e] * bj[e]; s1 += a1[e] * bj[e]; }
            acc0[j] += s0;
            acc1[j] += s1;
        }
        __syncthreads();
    }

    // lane-reduce each pair's partial and publish to sG
#pragma unroll
    for (int j = 0; j < NC; j++) {
        float s = acc0[j];
        for (int off = 16; off > 0; off >>= 1) s += __shfl_xor_sync(0xFFFFFFFFu, s, off);
        if (lid == 0) sG[i0 * NC + j] = s;
        float t = acc1[j];
        for (int off = 16; off > 0; off >>= 1) t += __shfl_xor_sync(0xFFFFFFFFu, t, off);
        if (lid == 0) sG[i1 * NC + j] = t;
    }
    __syncthreads();

    // distances: d(i,j) = sqrt(max(G[i][i] + G[j][j] - 2 G[i][j], 1e-12))
    {
        int i = tid >> 4, j = tid & 15;          // tid < 256 == NC*NC
        float d2 = sG[i * NC + i] + sG[j * NC + j] - 2.0f * sG[tid];
        sD[tid] = sqrtf(fmaxf(d2, 1e-12f));
    }
    __syncthreads();

    // ---- Phase 3: evaluate this block's triplet slice ---------------------
    float rsum = 0.f, psum = 0.f;
    unsigned cnt = 0;
    for (int t = bid * NTHR + tid; t < T; t += GRIDB * NTHR) {
        int a = ua[3 * t + 0];
        int p = ua[3 * t + 1];
        int n = ua[3 * t + 2];
        unsigned ca = (unsigned)a, cp = (unsigned)p, cn = (unsigned)n;
        bool ok = (ca < NC) && (cp < NC) && (cn < NC) &&
                  (s_first[ca] < B) && (s_first[cp] < B) && (s_first[cn] < B);
        if (ok) {
            float dap = sD[(ca << 4) | cp];
            float dan = sD[(ca << 4) | cn];
            rsum += fmaxf(dap - dan + MARGIN_F, 0.0f);
            float sap = 1.0f / (dap + 1.0f);
            float san = 1.0f / (dan + 1.0f);
            psum += -logf(sap / (sap + san) + EPS_F);
            cnt++;
        }
    }
    for (int off = 16; off > 0; off >>= 1) {
        rsum += __shfl_down_sync(0xFFFFFFFFu, rsum, off);
        psum += __shfl_down_sync(0xFFFFFFFFu, psum, off);
        cnt  += __shfl_down_sync(0xFFFFFFFFu, cnt,  off);
    }
    if (lid == 0) { br[wid] = rsum; bp[wid] = psum; bc[wid] = cnt; }
    __syncthreads();

    // ---- Phase 4: publish partial; LAST block finalizes (no spin) ---------
    if (tid == 0) {
        float R = 0.f, P = 0.f;
        unsigned C = 0;
        for (int w = 0; w < NTHR / 32; w++) { R += br[w]; P += bp[w]; C += bc[w]; }
        g_pr[bid] = R;
        g_pp[bid] = P;
        g_pc[bid] = C;
        __threadfence();
        int done = atomicAdd(&g_done, 1);
        s_last = (done == GRIDB - 1) ? 1 : 0;
    }
    __syncthreads();

    if (s_last) {
        __threadfence();
        double r = 0.0, p = 0.0;
        unsigned long long c = 0;
        if (tid < GRIDB) {
            r = (double)ldcg_f(&g_pr[tid]);
            p = (double)ldcg_f(&g_pp[tid]);
            c = (unsigned long long)ldcg_u(&g_pc[tid]);
        }
        for (int off = 16; off > 0; off >>= 1) {
            r += __shfl_down_sync(0xFFFFFFFFu, r, off);
            p += __shfl_down_sync(0xFFFFFFFFu, p, off);
            c += __shfl_down_sync(0xFFFFFFFFu, c, off);
        }
        __shared__ double fr[NTHR / 32], fp[NTHR / 32];
        __shared__ unsigned long long fc[NTHR / 32];
        if (lid == 0) { fr[wid] = r; fp[wid] = p; fc[wid] = c; }
        __syncthreads();
        if (tid == 0) {
            double R = 0.0, P = 0.0;
            unsigned long long C = 0;
            for (int w = 0; w < NTHR / 32; w++) { R += fr[w]; P += fp[w]; C += fc[w]; }
            double nv = (double)C;
            if (nv < 1.0) nv = 1.0;
            float lh = (float)(R / nv);
            float lp = (float)(P / nv);
            if (out_n > 0) out[0] = lh + lp;     // W_HUMAN = W_PER = 1
            if (out_n > 1) out[1] = lh;
            if (out_n > 2) out[2] = lp;
            g_done = 0;                          // clean state for next replay
            __threadfence();
        }
    }
}

// ---------------- launch ----------------------------------------------------
// Inputs identified BY SIZE (robust to metadata ordering):
//   inputs       : largest element count              (4096*1024 = 4194304)
//   user_answers : only remaining size divisible by 3 (100000*3  = 300000)
//   targets_mat  : FIRST entry with the minimum size  (4096; targets_sub is
//                  the second 4096 entry, dict order preserved)
extern "C" void kernel_launch(void* const* d_in, const int* in_sizes, int n_in,
                              void* d_out, int out_size) {
    int idx_inputs = -1, idx_ua = -1, idx_tm = -1;
    int max_sz = -1;
    for (int i = 0; i < n_in; i++)
        if (in_sizes[i] > max_sz) { max_sz = in_sizes[i]; idx_inputs = i; }
    for (int i = 0; i < n_in; i++) {
        if (i == idx_inputs) continue;
        if ((in_sizes[i] % 3) == 0) { idx_ua = i; break; }
    }
    int min_sz = 0x7fffffff;
    for (int i = 0; i < n_in; i++) {
        if (i == idx_inputs || i == idx_ua) continue;
        if (in_sizes[i] < min_sz) min_sz = in_sizes[i];
    }
    for (int i = 0; i < n_in; i++) {
        if (i == idx_inputs || i == idx_ua) continue;
        if (in_sizes[i] == min_sz) { idx_tm = i; break; }   // first occurrence
    }
    if (idx_inputs < 0 || idx_ua < 0 || idx_tm < 0) return;

    const float* inputs   = (const float*)d_in[idx_inputs];
    const int*   targets  = (const int*)d_in[idx_tm];
    const int*   user_ans = (const int*)d_in[idx_ua];
    float* out = (float*)d_out;

    int B = in_sizes[idx_tm];
    int D = in_sizes[idx_inputs] / B;
    int T = in_sizes[idx_ua] / 3;

    k_all<<<GRIDB, NTHR>>>(inputs, targets, user_ans, out, B, D, T, out_size);
}

// round 11
// speedup vs baseline: 2.0422x; 2.0422x over previous
#include <cuda_runtime.h>
#include <math.h>

#define NC       16
#define MARGIN_F 0.3f
#define EPS_F    1e-8f
#define NTHR     256
#define NDISTB   17                 // 17 blocks x 8 warps = 136 = #pairs i<=j
#define NEVAL    131
#define GRID     (NDISTB + NEVAL)   // 148 blocks = one wave, all co-resident
#define PF       3                  // prefetched triplets per eval thread

// ---------------- device-global scratch (no allocations allowed) -----------
__device__ float        g_D16[NC * NC];
__device__ int          g_pres;          // presence bitmask (written redundantly)
__device__ float        g_pr[NEVAL];
__device__ float        g_pp[NEVAL];
__device__ unsigned int g_pc[NEVAL];
__device__ int          g_dist_cnt = 0;  // reset by finalizer each run
__device__ int          g_done     = 0;

__device__ __forceinline__ float ldcg_f(const float* p) {
    float v; asm volatile("ld.global.cg.f32 %0, [%1];" : "=f"(v) : "l"(p)); return v;
}
__device__ __forceinline__ int ldcg_i(const int* p) {
    int v; asm volatile("ld.global.cg.s32 %0, [%1];" : "=r"(v) : "l"(p)); return v;
}
__device__ __forceinline__ unsigned ldcg_u(const unsigned* p) {
    unsigned v; asm volatile("ld.global.cg.u32 %0, [%1];" : "=r"(v) : "l"(p)); return v;
}
__device__ __forceinline__ void stcg_f(float* p, float v) {
    asm volatile("st.global.cg.f32 [%0], %1;" :: "l"(p), "f"(v) : "memory");
}

__global__ void __launch_bounds__(NTHR) k_all(
    const float* __restrict__ x,        // inputs [B, D]
    const int*   __restrict__ targets,  // targets_mat [B] (int32: JAX downcast)
    const int*   __restrict__ ua,       // user_answers [T,3] (int32)
    float*       __restrict__ out,
    int B, int D, int T, int out_n)
{
    const int tid = threadIdx.x;
    const int bid = blockIdx.x;
    const int wid = tid >> 5;
    const int lid = tid & 31;

    // ======================= DIST BLOCKS: bid < NDISTB ======================
    if (bid < NDISTB) {
        __shared__ int s_first[NC];
        __shared__ int s_flag;

        // early-exit first-occurrence scan (1 chunk whp)
        if (tid < NC) s_first[tid] = B;
        __syncthreads();
        for (int base = 0; base < B; base += NTHR) {
            int i = base + tid;
            if (i < B) {
                unsigned c = (unsigned)targets[i];
                if (c < NC && i < s_first[c]) atomicMin(&s_first[c], i);
            }
            __syncthreads();
            if (tid == 0) {
                int nf = 0;
#pragma unroll
                for (int k = 0; k < NC; k++) nf += (s_first[k] < B) ? 1 : 0;
                s_flag = (nf == NC) ? 1 : 0;
            }
            __syncthreads();
            if (s_flag) break;
        }

        // warp-per-pair dot: pair index q in [0,136), i<=j triangular decode
        int q = bid * 8 + wid;
        if (q < 136) {
            int i = 0, off = 0;
            while (q >= off + (NC - i)) { off += NC - i; i++; }
            int j = i + (q - off);

            int fi = s_first[i]; if (fi >= B) fi = 0;   // all-false argmax == 0
            int fj = s_first[j]; if (fj >= B) fj = 0;
            const float* xi = x + (size_t)fi * (size_t)D;
            const float* xj = x + (size_t)fj * (size_t)D;

            float sii = 0.f, sjj = 0.f, sij = 0.f;
            int nv4 = D >> 2;
            const float4* xi4 = (const float4*)xi;
            const float4* xj4 = (const float4*)xj;
            for (int k = lid; k < nv4; k += 32) {       // D=1024 -> 8 iters/lane
                float4 a = xi4[k];
                float4 b = xj4[k];
                sii += a.x * a.x + a.y * a.y + a.z * a.z + a.w * a.w;
                sjj += b.x * b.x + b.y * b.y + b.z * b.z + b.w * b.w;
                sij += a.x * b.x + a.y * b.y + a.z * b.z + a.w * b.w;
            }
            for (int k = (nv4 << 2) + lid; k < D; k += 32) {   // tail (D%4)
                float a = xi[k], b = xj[k];
                sii += a * a; sjj += b * b; sij += a * b;
            }
            for (int o = 16; o > 0; o >>= 1) {
                sii += __shfl_xor_sync(0xFFFFFFFFu, sii, o);
                sjj += __shfl_xor_sync(0xFFFFFFFFu, sjj, o);
                sij += __shfl_xor_sync(0xFFFFFFFFu, sij, o);
            }
            if (lid == 0) {
                float d2 = fmaxf(sii + sjj - 2.0f * sij, 1e-12f);
                float d = sqrtf(d2);
                stcg_f(&g_D16[i * NC + j], d);          // mirrored publish
                stcg_f(&g_D16[j * NC + i], d);
            }
        }
        __syncthreads();
        if (tid == 0) {
            int mask = 0;
#pragma unroll
            for (int k = 0; k < NC; k++) mask |= (s_first[k] < B) ? (1 << k) : 0;
            g_pres = mask;                               // identical in all blocks
            __threadfence();
            atomicAdd(&g_dist_cnt, 1);
        }
        return;
    }

    // ========================= EVAL BLOCKS ==================================
    __shared__ float sD[NC * NC];
    __shared__ int   s_pres;
    __shared__ float br[NTHR / 32], bp[NTHR / 32];
    __shared__ unsigned bc[NTHR / 32];
    __shared__ int   s_last;

    const int eb = bid - NDISTB;                 // 0..NEVAL-1
    const int STRIDE = NEVAL * NTHR;

    // Phase A: prefetch triplets into registers (hides under producer path)
    int t0 = eb * NTHR + tid;
    int ta[PF], tp[PF], tn[PF];
#pragma unroll
    for (int u = 0; u < PF; u++) {
        int t = t0 + u * STRIDE;
        if (t < T) {
            ta[u] = ua[3 * t + 0];
            tp[u] = ua[3 * t + 1];
            tn[u] = ua[3 * t + 2];
        } else {
            ta[u] = -1; tp[u] = -1; tn[u] = -1;
        }
    }

    // Phase B: wait for dist producers (plain-load spin; one-wave grid)
    if (tid == 0) {
        volatile int* vd = &g_dist_cnt;
        while (*vd < NDISTB) { __nanosleep(32); }
    }
    __syncthreads();
    __threadfence();
    sD[tid] = ldcg_f(&g_D16[tid]);               // tid < 256 == NC*NC
    if (tid == 0) s_pres = ldcg_i(&g_pres);
    __syncthreads();
    const int mask = s_pres;

    // Phase C: evaluate (2 MUFU per triplet: fdividef + logf)
    float rsum = 0.f, psum = 0.f;
    unsigned cnt = 0;
#pragma unroll
    for (int u = 0; u < PF; u++) {
        unsigned ca = (unsigned)ta[u], cp = (unsigned)tp[u], cn = (unsigned)tn[u];
        bool ok = (ca < NC) && (cp < NC) && (cn < NC) &&
                  (((mask >> ca) & (mask >> cp) & (mask >> cn)) & 1);
        if (ok) {
            float dap = sD[(ca << 4) | cp];
            float dan = sD[(ca << 4) | cn];
            rsum += fmaxf(dap - dan + MARGIN_F, 0.0f);
            // p_ap = sap/(sap+san) == (1+dan)/(2+dap+dan)
            float p = __fdividef(1.0f + dan, 2.0f + dap + dan);
            psum += -__logf(p + EPS_F);
            cnt++;
        }
    }
    for (int t = t0 + PF * STRIDE; t < T; t += STRIDE) {   // shape safety net
        unsigned ca = (unsigned)ua[3 * t + 0];
        unsigned cp = (unsigned)ua[3 * t + 1];
        unsigned cn = (unsigned)ua[3 * t + 2];
        bool ok = (ca < NC) && (cp < NC) && (cn < NC) &&
                  (((mask >> ca) & (mask >> cp) & (mask >> cn)) & 1);
        if (ok) {
            float dap = sD[(ca << 4) | cp];
            float dan = sD[(ca << 4) | cn];
            rsum += fmaxf(dap - dan + MARGIN_F, 0.0f);
            float p = __fdividef(1.0f + dan, 2.0f + dap + dan);
            psum += -__logf(p + EPS_F);
            cnt++;
        }
    }
    for (int o = 16; o > 0; o >>= 1) {
        rsum += __shfl_down_sync(0xFFFFFFFFu, rsum, o);
        psum += __shfl_down_sync(0xFFFFFFFFu, psum, o);
        cnt  += __shfl_down_sync(0xFFFFFFFFu, cnt,  o);
    }
    if (lid == 0) { br[wid] = rsum; bp[wid] = psum; bc[wid] = cnt; }
    __syncthreads();

    // Phase D: publish partial; last eval block finalizes (no spin)
    if (tid == 0) {
        float R = 0.f, P = 0.f;
        unsigned C = 0;
        for (int w = 0; w < NTHR / 32; w++) { R += br[w]; P += bp[w]; C += bc[w]; }
        g_pr[eb] = R;
        g_pp[eb] = P;
        g_pc[eb] = C;
        __threadfence();
        int done = atomicAdd(&g_done, 1);
        s_last = (done == NEVAL - 1) ? 1 : 0;
    }
    __syncthreads();

    if (s_last) {
        __threadfence();
        double r = 0.0, p = 0.0;
        unsigned long long c = 0;
        if (tid < NEVAL) {
            r = (double)ldcg_f(&g_pr[tid]);
            p = (double)ldcg_f(&g_pp[tid]);
            c = (unsigned long long)ldcg_u(&g_pc[tid]);
        }
        for (int o = 16; o > 0; o >>= 1) {
            r += __shfl_down_sync(0xFFFFFFFFu, r, o);
            p += __shfl_down_sync(0xFFFFFFFFu, p, o);
            c += __shfl_down_sync(0xFFFFFFFFu, c, o);
        }
        __shared__ double fr[NTHR / 32], fp[NTHR / 32];
        __shared__ unsigned long long fc[NTHR / 32];
        if (lid == 0) { fr[wid] = r; fp[wid] = p; fc[wid] = c; }
        __syncthreads();
        if (tid == 0) {
            double R = 0.0, P = 0.0;
            unsigned long long C = 0;
            for (int w = 0; w < NTHR / 32; w++) { R += fr[w]; P += fp[w]; C += fc[w]; }
            double nv = (double)C;
            if (nv < 1.0) nv = 1.0;
            float lh = (float)(R / nv);
            float lp = (float)(P / nv);
            if (out_n > 0) out[0] = lh + lp;     // W_HUMAN = W_PER = 1
            if (out_n > 1) out[1] = lh;
            if (out_n > 2) out[2] = lp;
            g_dist_cnt = 0;                       // clean state for next replay
            g_done     = 0;
            __threadfence();
        }
    }
}

// ---------------- launch ----------------------------------------------------
// Inputs identified BY SIZE (robust to metadata ordering):
//   inputs       : largest element count              (4096*1024 = 4194304)
//   user_answers : only remaining size divisible by 3 (100000*3  = 300000)
//   targets_mat  : FIRST entry with the minimum size  (4096; targets_sub is
//                  the second 4096 entry, dict order preserved)
extern "C" void kernel_launch(void* const* d_in, const int* in_sizes, int n_in,
                              void* d_out, int out_size) {
    int idx_inputs = -1, idx_ua = -1, idx_tm = -1;
    int max_sz = -1;
    for (int i = 0; i < n_in; i++)
        if (in_sizes[i] > max_sz) { max_sz = in_sizes[i]; idx_inputs = i; }
    for (int i = 0; i < n_in; i++) {
        if (i == idx_inputs) continue;
        if ((in_sizes[i] % 3) == 0) { idx_ua = i; break; }
    }
    int min_sz = 0x7fffffff;
    for (int i = 0; i < n_in; i++) {
        if (i == idx_inputs || i == idx_ua) continue;
        if (in_sizes[i] < min_sz) min_sz = in_sizes[i];
    }
    for (int i = 0; i < n_in; i++) {
        if (i == idx_inputs || i == idx_ua) continue;
        if (in_sizes[i] == min_sz) { idx_tm = i; break; }   // first occurrence
    }
    if (idx_inputs < 0 || idx_ua < 0 || idx_tm < 0) return;

    const float* inputs   = (const float*)d_in[idx_inputs];
    const int*   targets  = (const int*)d_in[idx_tm];
    const int*   user_ans = (const int*)d_in[idx_ua];
    float* out = (float*)d_out;

    int B = in_sizes[idx_tm];
    int D = in_sizes[idx_inputs] / B;
    int T = in_sizes[idx_ua] / 3;

    k_all<<<GRID, NTHR>>>(inputs, targets, user_ans, out, B, D, T, out_size);
}

// round 14
// speedup vs baseline: 2.3033x; 1.1278x over previous
#include <cuda_runtime.h>
#include <math.h>

#define NC       16
#define MARGIN_F 0.3f
#define EPS_F    1e-8f
#define NTHR     256
#define NDISTB   17                 // 17 blocks x 8 warps = 136 = #pairs i<=j
#define NEVAL    131
#define GRID     (NDISTB + NEVAL)   // 148 blocks = one wave, all co-resident
#define PF       3                  // prefetched triplets per eval thread

// ---------------- device-global scratch (no allocations allowed) -----------
__device__ float        g_D16[NC * NC];
__device__ int          g_pres;          // presence bitmask (written redundantly)
__device__ float        g_pr[NEVAL];
__device__ float        g_pp[NEVAL];
__device__ unsigned int g_pc[NEVAL];
__device__ int          g_dist_cnt = 0;  // reset by finalizer each run
__device__ int          g_done     = 0;

__device__ __forceinline__ float ldcg_f(const float* p) {
    float v; asm volatile("ld.global.cg.f32 %0, [%1];" : "=f"(v) : "l"(p)); return v;
}
__device__ __forceinline__ int ldcg_i(const int* p) {
    int v; asm volatile("ld.global.cg.s32 %0, [%1];" : "=r"(v) : "l"(p)); return v;
}
__device__ __forceinline__ unsigned ldcg_u(const unsigned* p) {
    unsigned v; asm volatile("ld.global.cg.u32 %0, [%1];" : "=r"(v) : "l"(p)); return v;
}
__device__ __forceinline__ void stcg_f(float* p, float v) {
    asm volatile("st.global.cg.f32 [%0], %1;" :: "l"(p), "f"(v) : "memory");
}
// release-annotated fire-and-forget add: orders all prior stores, no fence needed
__device__ __forceinline__ void red_release_add(int* p, int v) {
    asm volatile("red.release.gpu.global.add.s32 [%0], %1;" :: "l"(p), "r"(v) : "memory");
}
// acquire load for the spin: orders subsequent loads, no fence needed
__device__ __forceinline__ int ld_acquire(const int* p) {
    int v; asm volatile("ld.acquire.gpu.global.s32 %0, [%1];" : "=r"(v) : "l"(p)); return v;
}
// acq_rel RMW returning old value: release own stores + acquire others'
__device__ __forceinline__ int atom_acqrel_add(int* p, int v) {
    int o; asm volatile("atom.acq_rel.gpu.global.add.s32 %0, [%1], %2;"
                        : "=r"(o) : "l"(p), "r"(v) : "memory");
    return o;
}

__global__ void __launch_bounds__(NTHR) k_all(
    const float* __restrict__ x,        // inputs [B, D]
    const int*   __restrict__ targets,  // targets_mat [B] (int32: JAX downcast)
    const int*   __restrict__ ua,       // user_answers [T,3] (int32)
    float*       __restrict__ out,
    int B, int D, int T, int out_n)
{
    const int tid = threadIdx.x;
    const int bid = blockIdx.x;
    const int wid = tid >> 5;
    const int lid = tid & 31;

    // ======================= DIST BLOCKS: bid < NDISTB ======================
    if (bid < NDISTB) {
        __shared__ int s_first[NC];
        __shared__ int s_flag;

        // early-exit first-occurrence scan (1 chunk whp)
        if (tid < NC) s_first[tid] = B;
        __syncthreads();
        for (int base = 0; base < B; base += NTHR) {
            int i = base + tid;
            if (i < B) {
                unsigned c = (unsigned)targets[i];
                if (c < NC && i < s_first[c]) atomicMin(&s_first[c], i);
            }
            __syncthreads();
            if (tid == 0) {
                int nf = 0;
#pragma unroll
                for (int k = 0; k < NC; k++) nf += (s_first[k] < B) ? 1 : 0;
                s_flag = (nf == NC) ? 1 : 0;
            }
            __syncthreads();
            if (s_flag) break;
        }

        // warp-per-pair dot: pair index q in [0,136), i<=j triangular decode
        int q = bid * 8 + wid;
        if (q < 136) {
            int i = 0, off = 0;
            while (q >= off + (NC - i)) { off += NC - i; i++; }
            int j = i + (q - off);

            int fi = s_first[i]; if (fi >= B) fi = 0;   // all-false argmax == 0
            int fj = s_first[j]; if (fj >= B) fj = 0;
            const float* xi = x + (size_t)fi * (size_t)D;
            const float* xj = x + (size_t)fj * (size_t)D;

            float sii = 0.f, sjj = 0.f, sij = 0.f;
            int nv4 = D >> 2;
            const float4* xi4 = (const float4*)xi;
            const float4* xj4 = (const float4*)xj;
            for (int k = lid; k < nv4; k += 32) {       // D=1024 -> 8 iters/lane
                float4 a = xi4[k];
                float4 b = xj4[k];
                sii += a.x * a.x + a.y * a.y + a.z * a.z + a.w * a.w;
                sjj += b.x * b.x + b.y * b.y + b.z * b.z + b.w * b.w;
                sij += a.x * b.x + a.y * b.y + a.z * b.z + a.w * b.w;
            }
            for (int k = (nv4 << 2) + lid; k < D; k += 32) {   // tail (D%4)
                float a = xi[k], b = xj[k];
                sii += a * a; sjj += b * b; sij += a * b;
            }
            for (int o = 16; o > 0; o >>= 1) {
                sii += __shfl_xor_sync(0xFFFFFFFFu, sii, o);
                sjj += __shfl_xor_sync(0xFFFFFFFFu, sjj, o);
                sij += __shfl_xor_sync(0xFFFFFFFFu, sij, o);
            }
            if (lid == 0) {
                float d2 = fmaxf(sii + sjj - 2.0f * sij, 1e-12f);
                float d = sqrtf(d2);
                stcg_f(&g_D16[i * NC + j], d);          // mirrored publish
                stcg_f(&g_D16[j * NC + i], d);
            }
        }
        __syncthreads();
        if (tid == 0) {
            int mask = 0;
#pragma unroll
            for (int k = 0; k < NC; k++) mask |= (s_first[k] < B) ? (1 << k) : 0;
            g_pres = mask;                               // identical in all blocks
            red_release_add(&g_dist_cnt, 1);             // release: no fence needed
        }
        return;
    }

    // ========================= EVAL BLOCKS ==================================
    __shared__ float sD[NC * NC];
    __shared__ int   s_pres;
    __shared__ float br[NTHR / 32], bp[NTHR / 32];
    __shared__ unsigned bc[NTHR / 32];
    __shared__ int   s_last;

    const int eb = bid - NDISTB;                 // 0..NEVAL-1
    const int STRIDE = NEVAL * NTHR;

    // Phase A: prefetch triplets into registers (hides under producer path)
    int t0 = eb * NTHR + tid;
    int ta[PF], tp[PF], tn[PF];
#pragma unroll
    for (int u = 0; u < PF; u++) {
        int t = t0 + u * STRIDE;
        if (t < T) {
            ta[u] = ua[3 * t + 0];
            tp[u] = ua[3 * t + 1];
            tn[u] = ua[3 * t + 2];
        } else {
            ta[u] = -1; tp[u] = -1; tn[u] = -1;
        }
    }

    // Phase B: wait for dist producers (acquire-load spin; one-wave grid)
    if (tid == 0) {
        while (ld_acquire(&g_dist_cnt) < NDISTB) { __nanosleep(32); }
    }
    __syncthreads();
    sD[tid] = ldcg_f(&g_D16[tid]);               // tid < 256 == NC*NC
    if (tid == 0) s_pres = ldcg_i(&g_pres);
    __syncthreads();
    const int mask = s_pres;

    // Phase C: evaluate (2 MUFU per triplet: fdividef + logf)
    float rsum = 0.f, psum = 0.f;
    unsigned cnt = 0;
#pragma unroll
    for (int u = 0; u < PF; u++) {
        unsigned ca = (unsigned)ta[u], cp = (unsigned)tp[u], cn = (unsigned)tn[u];
        bool ok = (ca < NC) && (cp < NC) && (cn < NC) &&
                  (((mask >> ca) & (mask >> cp) & (mask >> cn)) & 1);
        if (ok) {
            float dap = sD[(ca << 4) | cp];
            float dan = sD[(ca << 4) | cn];
            rsum += fmaxf(dap - dan + MARGIN_F, 0.0f);
            // p_ap = sap/(sap+san) == (1+dan)/(2+dap+dan)
            float p = __fdividef(1.0f + dan, 2.0f + dap + dan);
            psum += -__logf(p + EPS_F);
            cnt++;
        }
    }
    for (int t = t0 + PF * STRIDE; t < T; t += STRIDE) {   // shape safety net
        unsigned ca = (unsigned)ua[3 * t + 0];
        unsigned cp = (unsigned)ua[3 * t + 1];
        unsigned cn = (unsigned)ua[3 * t + 2];
        bool ok = (ca < NC) && (cp < NC) && (cn < NC) &&
                  (((mask >> ca) & (mask >> cp) & (mask >> cn)) & 1);
        if (ok) {
            float dap = sD[(ca << 4) | cp];
            float dan = sD[(ca << 4) | cn];
            rsum += fmaxf(dap - dan + MARGIN_F, 0.0f);
            float p = __fdividef(1.0f + dan, 2.0f + dap + dan);
            psum += -__logf(p + EPS_F);
            cnt++;
        }
    }
    for (int o = 16; o > 0; o >>= 1) {
        rsum += __shfl_down_sync(0xFFFFFFFFu, rsum, o);
        psum += __shfl_down_sync(0xFFFFFFFFu, psum, o);
        cnt  += __shfl_down_sync(0xFFFFFFFFu, cnt,  o);
    }
    if (lid == 0) { br[wid] = rsum; bp[wid] = psum; bc[wid] = cnt; }
    __syncthreads();

    // Phase D: publish partial; last eval block finalizes (no spin)
    if (tid == 0) {
        float R = 0.f, P = 0.f;
        unsigned C = 0;
        for (int w = 0; w < NTHR / 32; w++) { R += br[w]; P += bp[w]; C += bc[w]; }
        g_pr[eb] = R;
        g_pp[eb] = P;
        g_pc[eb] = C;
        int done = atom_acqrel_add(&g_done, 1);  // release own stores, acquire others'
        s_last = (done == NEVAL - 1) ? 1 : 0;
    }
    __syncthreads();

    if (s_last) {
        double r = 0.0, p = 0.0;
        unsigned long long c = 0;
        if (tid < NEVAL) {
            r = (double)ldcg_f(&g_pr[tid]);
            p = (double)ldcg_f(&g_pp[tid]);
            c = (unsigned long long)ldcg_u(&g_pc[tid]);
        }
        for (int o = 16; o > 0; o >>= 1) {
            r += __shfl_down_sync(0xFFFFFFFFu, r, o);
            p += __shfl_down_sync(0xFFFFFFFFu, p, o);
            c += __shfl_down_sync(0xFFFFFFFFu, c, o);
        }
        __shared__ double fr[NTHR / 32], fp[NTHR / 32];
        __shared__ unsigned long long fc[NTHR / 32];
        if (lid == 0) { fr[wid] = r; fp[wid] = p; fc[wid] = c; }
        __syncthreads();
        if (tid == 0) {
            double R = 0.0, P = 0.0;
            unsigned long long C = 0;
            for (int w = 0; w < NTHR / 32; w++) { R += fr[w]; P += fp[w]; C += fc[w]; }
            double nv = (double)C;
            if (nv < 1.0) nv = 1.0;
            float lh = (float)(R / nv);
            float lp = (float)(P / nv);
            if (out_n > 0) out[0] = lh + lp;     // W_HUMAN = W_PER = 1
            if (out_n > 1) out[1] = lh;
            if (out_n > 2) out[2] = lp;
            g_dist_cnt = 0;                       // clean state for next replay
            g_done     = 0;
            __threadfence();
        }
    }
}

// ---------------- launch ----------------------------------------------------
// Inputs identified BY SIZE (robust to metadata ordering):
//   inputs       : largest element count              (4096*1024 = 4194304)
//   user_answers : only remaining size divisible by 3 (100000*3  = 300000)
//   targets_mat  : FIRST entry with the minimum size  (4096; targets_sub is
//                  the second 4096 entry, dict order preserved)
extern "C" void kernel_launch(void* const* d_in, const int* in_sizes, int n_in,
                              void* d_out, int out_size) {
    int idx_inputs = -1, idx_ua = -1, idx_tm = -1;
    int max_sz = -1;
    for (int i = 0; i < n_in; i++)
        if (in_sizes[i] > max_sz) { max_sz = in_sizes[i]; idx_inputs = i; }
    for (int i = 0; i < n_in; i++) {
        if (i == idx_inputs) continue;
        if ((in_sizes[i] % 3) == 0) { idx_ua = i; break; }
    }
    int min_sz = 0x7fffffff;
    for (int i = 0; i < n_in; i++) {
        if (i == idx_inputs || i == idx_ua) continue;
        if (in_sizes[i] < min_sz) min_sz = in_sizes[i];
    }
    for (int i = 0; i < n_in; i++) {
        if (i == idx_inputs || i == idx_ua) continue;
        if (in_sizes[i] == min_sz) { idx_tm = i; break; }   // first occurrence
    }
    if (idx_inputs < 0 || idx_ua < 0 || idx_tm < 0) return;

    const float* inputs   = (const float*)d_in[idx_inputs];
    const int*   targets  = (const int*)d_in[idx_tm];
    const int*   user_ans = (const int*)d_in[idx_ua];
    float* out = (float*)d_out;

    int B = in_sizes[idx_tm];
    int D = in_sizes[idx_inputs] / B;
    int T = in_sizes[idx_ua] / 3;

    k_all<<<GRID, NTHR>>>(inputs, targets, user_ans, out, B, D, T, out_size);
}